// round 3
// baseline (speedup 1.0000x reference)
#include <cuda_runtime.h>
#include <cstdint>

// Problem constants (match reference_code)
#define NU 100000
#define NI 50000
#define NE 1000000
#define EMB 64
#define DV 16   // float4 chunks per embedding row (64/4)

// ---------------------------------------------------------------------------
// Scratch: __device__ globals (no allocation allowed in kernel_launch)
// ---------------------------------------------------------------------------
__device__ float g_accU[NU * EMB];   // sum of item rows scattered to users
__device__ float g_accI[NI * EMB];   // sum of user rows scattered to items
__device__ float g_u1[NU * EMB];     // round-1 user output
__device__ float g_i1[NI * EMB];     // round-1 item output
__device__ float g_invU[NU];
__device__ float g_invI[NI];
__device__ int   g_degU[NU];
__device__ int   g_degI[NI];

// Vectorized global fp32 reduction (sm_90+): one L2 op per 16 bytes.
__device__ __forceinline__ void red_add_v4(float* p, float4 v) {
    asm volatile("red.global.add.v4.f32 [%0], {%1, %2, %3, %4};"
                 :: "l"(p), "f"(v.x), "f"(v.y), "f"(v.z), "f"(v.w)
                 : "memory");
}

// ---------------------------------------------------------------------------
// Kernels
// ---------------------------------------------------------------------------

// Zero all per-launch scratch (acc buffers + degree counters).
__global__ void zero_scratch() {
    int64_t total = (int64_t)(NU + NI) * EMB;          // floats in acc buffers
    int64_t stride = (int64_t)gridDim.x * blockDim.x;
    for (int64_t i = (int64_t)blockIdx.x * blockDim.x + threadIdx.x; i < total; i += stride) {
        if (i < (int64_t)NU * EMB) g_accU[i] = 0.0f;
        else                       g_accI[i - (int64_t)NU * EMB] = 0.0f;
    }
    for (int64_t i = (int64_t)blockIdx.x * blockDim.x + threadIdx.x; i < NU + NI; i += stride) {
        if (i < NU) g_degU[i] = 0;
        else        g_degI[i - NU] = 0;
    }
}

__global__ void degree_kernel(const int* __restrict__ es, const int* __restrict__ ed) {
    int e = blockIdx.x * blockDim.x + threadIdx.x;
    if (e < NE) {
        atomicAdd(&g_degU[es[e]], 1);
        atomicAdd(&g_degI[ed[e]], 1);
    }
}

__global__ void invdeg_kernel() {
    int i = blockIdx.x * blockDim.x + threadIdx.x;
    if (i < NU) {
        int d = g_degU[i];
        g_invU[i] = (d > 0) ? (1.0f / (float)d) : 0.0f;
    }
    if (i < NI) {
        int d = g_degI[i];
        g_invI[i] = (d > 0) ? (1.0f / (float)d) : 0.0f;
    }
}

// Both aggregation directions in one pass.
// 16 threads per edge; thread handles one float4 (16B) of the 256B row.
// 16 consecutive lanes cover one contiguous row -> fully coalesced gathers
// and contiguous 256B vector-RED scatters.
__global__ void aggregate_kernel(const float4* __restrict__ urow,
                                 const float4* __restrict__ irow,
                                 const int*    __restrict__ es,
                                 const int*    __restrict__ ed) {
    int t = blockIdx.x * blockDim.x + threadIdx.x;
    int e = t >> 4;
    int c = t & 15;
    if (e >= NE) return;
    int s = es[e];   // user index (broadcast load: 16 lanes same address)
    int d = ed[e];   // item index
    float4 uv = urow[(int64_t)s * DV + c];   // user row chunk -> scatter to item acc
    float4 iv = irow[(int64_t)d * DV + c];   // item row chunk -> scatter to user acc
    red_add_v4(&g_accI[(int64_t)d * EMB + c * 4], uv);
    red_add_v4(&g_accU[(int64_t)s * EMB + c * 4], iv);
}

// out = acc * inv_deg[row] + in * sw[row]; optionally re-zero acc for next round.
__global__ void finalize_kernel(const float4* __restrict__ uin,
                                const float4* __restrict__ iin,
                                const float*  __restrict__ usw,
                                const float*  __restrict__ isw,
                                float4* __restrict__ uout,
                                float4* __restrict__ iout,
                                int resetAcc) {
    int t = blockIdx.x * blockDim.x + threadIdx.x;
    const int utotal = NU * DV;
    const int itotal = NI * DV;
    if (t < utotal) {
        int row = t >> 4;  // t / DV
        float inv = g_invU[row];
        float sw  = usw[row];
        float4* acc4 = reinterpret_cast<float4*>(g_accU);
        float4 a = acc4[t];
        float4 x = uin[t];
        float4 r;
        r.x = a.x * inv + x.x * sw;
        r.y = a.y * inv + x.y * sw;
        r.z = a.z * inv + x.z * sw;
        r.w = a.w * inv + x.w * sw;
        uout[t] = r;
        if (resetAcc) acc4[t] = make_float4(0.f, 0.f, 0.f, 0.f);
    } else if (t < utotal + itotal) {
        int j = t - utotal;
        int row = j >> 4;
        float inv = g_invI[row];
        float sw  = isw[row];
        float4* acc4 = reinterpret_cast<float4*>(g_accI);
        float4 a = acc4[j];
        float4 x = iin[j];
        float4 r;
        r.x = a.x * inv + x.x * sw;
        r.y = a.y * inv + x.y * sw;
        r.z = a.z * inv + x.z * sw;
        r.w = a.w * inv + x.w * sw;
        iout[j] = r;
        if (resetAcc) acc4[j] = make_float4(0.f, 0.f, 0.f, 0.f);
    }
}

// ---------------------------------------------------------------------------
// Launch
// ---------------------------------------------------------------------------
extern "C" void kernel_launch(void* const* d_in, const int* in_sizes, int n_in,
                              void* d_out, int out_size) {
    const float* user_emb = (const float*)d_in[0];   // [NU, 64]
    const float* item_emb = (const float*)d_in[1];   // [NI, 64]
    const float* u_sw     = (const float*)d_in[2];   // [NU, 1]
    const float* i_sw     = (const float*)d_in[3];   // [NI, 1]
    const int*   e_src    = (const int*)d_in[4];     // [NE]
    const int*   e_dst    = (const int*)d_in[5];     // [NE]

    float* out_u = (float*)d_out;                    // [NU, 64]
    float* out_i = (float*)d_out + (int64_t)NU * EMB; // [NI, 64]

    // Resolve device-global scratch addresses for kernel args
    float4* g_u1_4 = nullptr; float4* g_i1_4 = nullptr;
    // (device symbols are directly addressable inside kernels; for passing as
    //  args we re-derive them in-kernel instead — see finalize/agg usage of
    //  globals. Only u1/i1 need to flow between kernels as pointers.)

    const int TPB = 256;

    // 1) zero scratch
    zero_scratch<<<1024, TPB>>>();

    // 2) degrees
    degree_kernel<<<(NE + TPB - 1) / TPB, TPB>>>(e_src, e_dst);

    // 3) inverse degrees
    invdeg_kernel<<<(NU + TPB - 1) / TPB, TPB>>>();

    // Round 1 aggregation: gather from (user_emb, item_emb)
    {
        int64_t threads = (int64_t)NE * DV;
        int blocks = (int)((threads + TPB - 1) / TPB);
        aggregate_kernel<<<blocks, TPB>>>((const float4*)user_emb,
                                          (const float4*)item_emb,
                                          e_src, e_dst);
    }

    // Round 1 finalize -> g_u1 / g_i1, reset acc
    {
        int threads = (NU + NI) * DV;
        int blocks = (threads + TPB - 1) / TPB;
        // get device pointers to g_u1 / g_i1 via a tiny trampoline: use
        // cudaGetSymbolAddress (host query; not a stream op, capture-safe)
        static float4* u1p = nullptr;
        static float4* i1p = nullptr;
        if (!u1p) {
            void* p;
            cudaGetSymbolAddress(&p, g_u1); u1p = (float4*)p;
            cudaGetSymbolAddress(&p, g_i1); i1p = (float4*)p;
        }
        g_u1_4 = u1p; g_i1_4 = i1p;
        finalize_kernel<<<blocks, TPB>>>((const float4*)user_emb,
                                         (const float4*)item_emb,
                                         u_sw, i_sw,
                                         g_u1_4, g_i1_4, /*resetAcc=*/1);
    }

    // Round 2 aggregation: gather from (u1, i1)
    {
        int64_t threads = (int64_t)NE * DV;
        int blocks = (int)((threads + TPB - 1) / TPB);
        aggregate_kernel<<<blocks, TPB>>>((const float4*)g_u1_4,
                                          (const float4*)g_i1_4,
                                          e_src, e_dst);
    }

    // Round 2 finalize -> d_out
    {
        int threads = (NU + NI) * DV;
        int blocks = (threads + TPB - 1) / TPB;
        finalize_kernel<<<blocks, TPB>>>((const float4*)g_u1_4,
                                         (const float4*)g_i1_4,
                                         u_sw, i_sw,
                                         (float4*)out_u, (float4*)out_i,
                                         /*resetAcc=*/0);
    }
}